// round 12
// baseline (speedup 1.0000x reference)
#include <cuda_runtime.h>
#include <math.h>

// ---------------- constants (from reference) ----------------
#define SPIN_LEN   100
#define TRAIN_LEN  200000
#define ML_C       2.9086f
#define SL_C       1.898f
#define L2E        1.4426950408889634f

#define CHT     4                    // output steps per thread
#define TB      128                  // threads per scan block (4 warps)
#define WARM    24                   // discarded convergence steps (multiple of 4)
#define OUTB    (TB * CHT)           // 512 output steps per block
#define NWB     (WARM + OUTB)        // 536-step shared input window per block
#define SK4(g)  ((g) + ((g) >> 3))   // float4 skew: conflict-free at stride 4
#define SWIN4   (SK4(NWB - 1) + 1)   // 602
#define SKO(t)  ((t) + ((t) >> 5))   // float skew for output transpose buffer
#define SOUT    (SKO(OUTB - 1) + 1)  // 527

#define STD_N   (TRAIN_LEN - SPIN_LEN)   // 199900 floats = 49975 float4 exactly
#define STD_N4  (STD_N / 4)              // 49975
#define SB      196                      // 196*256 = 50176 threads >= 49975

// ---------------- device scratch (zero-initialized) ----------------
__device__ float    g_ps[SB];
__device__ float    g_pq[SB];
__device__ unsigned g_tick;          // self-resetting ticket (graph-replay safe)
__device__ float4   g_P0;            // thr, oo1, ol1, a1n
__device__ float4   g_P1;            // k01n, a2n, k02n, obsstd

__device__ __forceinline__ float ex2f(float x) { float y; asm("ex2.approx.f32 %0, %1;" : "=f"(y) : "f"(x)); return y; }
__device__ __forceinline__ float rcpf(float x) { float y; asm("rcp.approx.f32 %0, %1;" : "=f"(y) : "f"(x)); return y; }

// ---------------- std pass 1 + last-block finalize (std and params) ----------
__global__ void __launch_bounds__(256)
k_std1(const float* __restrict__ y,
       const float* cmean, const float* cstd,
       const float* W_rom, const float* W_rlm, const float* W_rfm,
       const float* b0_yom, const float* W_b1_yom,
       const float* b0_ylm, const float* W_b2_ylm,
       const float* theltaC)
{
    __shared__ float ss[8], sq[8];
    __shared__ int   is_last;
    const int tid = threadIdx.x;
    const int gi  = blockIdx.x * 256 + tid;

    float a = 0.0f, b = 0.0f;
    if (gi < STD_N4) {
        // y + SPIN_LEN is 16B-aligned (100 floats = 400 bytes)
        float4 v = reinterpret_cast<const float4*>(y + SPIN_LEN)[gi];
        a = ((v.x + v.y) + (v.z + v.w));
        b = fmaf(v.x, v.x, fmaf(v.y, v.y, fmaf(v.z, v.z, v.w * v.w)));
    }
    #pragma unroll
    for (int o = 16; o > 0; o >>= 1) {
        a += __shfl_down_sync(0xffffffffu, a, o);
        b += __shfl_down_sync(0xffffffffu, b, o);
    }
    if ((tid & 31) == 0) { ss[tid >> 5] = a; sq[tid >> 5] = b; }
    __syncthreads();
    if (tid == 0) {
        float sa = 0.0f, sb = 0.0f;
        #pragma unroll
        for (int w = 0; w < 8; ++w) { sa += ss[w]; sb += sq[w]; }
        g_ps[blockIdx.x] = sa;
        g_pq[blockIdx.x] = sb;
        __threadfence();
        is_last = (atomicAdd(&g_tick, 1u) == SB - 1);
    }
    __syncthreads();

    if (is_last && tid < 32) {
        // deterministic fixed-order reduce over the 196 partials
        float sa = 0.0f, sb = 0.0f;
        for (int i = tid; i < SB; i += 32) { sa += g_ps[i]; sb += g_pq[i]; }
        #pragma unroll
        for (int o = 16; o > 0; o >>= 1) {
            sa += __shfl_down_sync(0xffffffffu, sa, o);
            sb += __shfl_down_sync(0xffffffffu, sb, o);
        }
        if (tid == 0) {
            const float n = (float)STD_N;
            float mean = sa / n;
            float stdv = sqrtf((sb - sa * mean) / (n - 1.0f));

            // derived scalar params
            float eo  = expf(W_rom[0]);
            float el  = expf(W_rlm[0]);
            float den = eo + el + expf(W_rfm[0]);
            float a1  = W_b1_yom[0] / cstd[0];
            float a2  = W_b2_ylm[0] / SL_C;
            g_P0 = make_float4(expf(theltaC[0]),            // thr
                               eo / den,                    // oo1
                               el / den,                    // ol1
                               -a1 * L2E);                  // a1n
            g_P1 = make_float4(-(b0_yom[0] - cmean[0] * a1) * L2E,  // k01n
                               -a2 * L2E,                           // a2n
                               -(b0_ylm[0] - ML_C * a2) * L2E,      // k02n
                               stdv);
            g_tick = 0;   // reset for next graph replay (all adds already done)
        }
    }
}

// ---------------- main chunked-warmup scan ----------------
// 512 blocks x 128 threads. Block shares one 536-step window (WARM prefix
// shared across all 128 chains). Thread t: 24 discarded + 4 emitted steps.
// Params/std arrive precomputed (2 broadcast float4 loads). Outputs go
// through a skewed smem transpose, flushed fully coalesced.
__global__ void __launch_bounds__(TB)
k_scan(const float* __restrict__ x, float* __restrict__ out, int B)
{
    __shared__ float4 sw[SWIN4];
    __shared__ float  ob[10 * SOUT];

    const int tid    = threadIdx.x;
    const int base   = blockIdx.x * OUTB;   // first emitted global step
    const int wstart = base - WARM;         // window start (may be < 0)

    // ---- issue x loads first (5 float2 per thread), params overlap ----
    float2 xv[5];
    #pragma unroll
    for (int m = 0; m < 5; ++m) {
        int g = tid + TB * m;
        int i = wstart + g;
        xv[m] = make_float2(0.0f, 0.0f);
        if (g < NWB && i >= 0)
            xv[m] = reinterpret_cast<const float2*>(x)[i];
    }
    const float4 P0 = g_P0, P1 = g_P1;      // broadcast loads (L2-hot)
    const float thr = P0.x, oo1 = P0.y, ol1 = P0.z, a1n = P0.w;
    const float k01n = P1.x, a2n = P1.y, k02n = P1.z, stdv = P1.w;

    // ---- stage window + precompute ol(u2) ----
    // Zero-fill for steps < 0 keeps c == 0 exactly (m=min(0,thr)=0, olcc=0).
    #pragma unroll
    for (int m = 0; m < 5; ++m) {
        int g = tid + TB * m;
        if (g < NWB) {
            float ol = ol1 * rcpf(1.0f + ex2f(fmaf(xv[m].y, a2n, k02n)));
            if (wstart + g < 0) ol = 0.0f;
            sw[SK4(g)] = make_float4(xv[m].x, xv[m].y, ol, 0.0f);
        }
    }
    __syncthreads();

    const int g0 = tid * CHT;          // chain window start (multiple of 4)
    float c = 0.0f;

    // ---- warmup: divide-free, affine smem addressing ----
    // 4-aligned 4-step ranges never cross an 8-boundary -> (g)>>3 constant
    // per range -> base pointer + immediate offsets.
    // step: m = min(u1, thr-c); olcc = min(ol*c, u2); c' = fma(-oo1*c, s, (c-olcc)+m)
    #pragma unroll
    for (int k0 = 0; k0 < WARM; k0 += 4) {
        const float4* p = &sw[SK4(g0 + k0)];
        #pragma unroll
        for (int k = 0; k < 4; ++k) {
            float4 v = p[k];
            float s    = rcpf(1.0f + ex2f(fmaf(c, a1n, k01n)));
            float t    = oo1 * c;
            float olcc = fminf(v.z * c, v.y);
            float m    = fminf(v.x, thr - c);
            c = fmaf(-t, s, (c - olcc) + m);
        }
    }

    // ---- output phase: 4 steps into smem transpose buffer ----
    const int sb0 = CHT * tid + (tid >> 3);   // SKO(4*tid), k-invariant base
    {
        const float4* p = &sw[SK4(g0 + WARM)];
        #pragma unroll
        for (int k = 0; k < CHT; ++k) {
            float4 v = p[k];
            float* q = &ob[sb0 + k];

            float s    = rcpf(1.0f + ex2f(fmaf(c, a1n, k01n)));
            float oo   = oo1 * s;
            float ooc  = oo * c;
            float olc  = (c > 0.0f) ? fminf(v.z, v.y * rcpf(c)) : v.z;
            float olcc = olc * c;
            float px   = fmaxf(v.x + c - thr, 0.0f);
            float ib   = (v.x > 0.0f) ? px * rcpf(v.x) : 0.0f;
            float f    = (1.0f - oo) - olc;

            q[0 * SOUT] = ooc + px;   // h_n
            q[1 * SOUT] = c;          // c_n (pre-update)
            q[2 * SOUT] = v.z * c;    // l_n
            q[3 * SOUT] = olcc;       // lc_n
            q[4 * SOUT] = px;         // bp_n
            q[5 * SOUT] = ib;         // g_ib
            q[6 * SOUT] = oo;         // g_oo
            q[7 * SOUT] = v.z;        // g_ol
            q[8 * SOUT] = olc;        // g_olc
            q[9 * SOUT] = f;          // g_f

            c = ((c - ooc) - olcc) + (v.x - px);
        }
    }
    __syncthreads();

    // ---- coalesced flush (also produces h_nout and obs_std streams) ----
    #pragma unroll
    for (int st = 0; st < 10; ++st) {
        #pragma unroll
        for (int m = 0; m < OUTB / TB; ++m) {
            int t = tid + TB * m;
            out[(size_t)st * B + base + t] = ob[st * SOUT + t + (t >> 5)];
        }
    }
    float2* o2 = reinterpret_cast<float2*>(out + 10 * (size_t)B);
    #pragma unroll
    for (int m = 0; m < OUTB / TB; ++m) {
        int t = tid + TB * m;
        o2[base + t] = make_float2(ob[t + (t >> 5)], stdv);   // h_nout = [h, std]
        out[12 * (size_t)B + base + t] = stdv;                // obs_std
    }
}

// ---------------- launch ----------------
extern "C" void kernel_launch(void* const* d_in, const int* in_sizes, int n_in,
                              void* d_out, int out_size)
{
    const float* x = (const float*)d_in[0];
    const float* y = (const float*)d_in[1];
    float* out = (float*)d_out;
    const int B = in_sizes[0] / 2;   // 262144

    k_std1<<<SB, 256>>>(y,
                        (const float*)d_in[2], (const float*)d_in[3],
                        (const float*)d_in[4], (const float*)d_in[5],
                        (const float*)d_in[6], (const float*)d_in[7],
                        (const float*)d_in[8], (const float*)d_in[9],
                        (const float*)d_in[10], (const float*)d_in[11]);

    const int blocks = B / OUTB;     // 512 blocks x 128 threads
    k_scan<<<blocks, TB>>>(x, out, B);
}

// round 13
// speedup vs baseline: 1.2145x; 1.2145x over previous
#include <cuda_runtime.h>
#include <math.h>

// ---------------- constants (from reference) ----------------
#define SPIN_LEN   100
#define TRAIN_LEN  200000
#define ML_C       2.9086f
#define SL_C       1.898f
#define L2E        1.4426950408889634f

#define CHT     4                    // output steps per thread
#define TB      128                  // threads per scan block (4 warps)
#define WARM    24                   // discarded convergence steps (multiple of 4)
#define OUTB    (TB * CHT)           // 512 output steps per block
#define NWB     (WARM + OUTB)        // 536-step shared input window per block
#define SK4(g)  ((g) + ((g) >> 3))   // float4 skew: conflict-free at stride 4
#define SWIN4   (SK4(NWB - 1) + 1)   // 602
#define SKO(t)  ((t) + ((t) >> 5))   // float skew for output transpose buffer
#define SOUT    (SKO(OUTB - 1) + 1)  // 527

#define STD_N   (TRAIN_LEN - SPIN_LEN)   // 199900 floats = 49975 float4 exactly
#define STD_N4  (STD_N / 4)              // 49975
#define SB      196                      // 196*256 = 50176 threads >= 49975

// ---------------- device scratch ----------------
__device__ float  g_ps[SB];
__device__ float  g_pq[SB];
__device__ float4 g_P0;              // thr, oo1, ol1, a1n
__device__ float4 g_P1;              // k01n, a2n, k02n, (unused)

__device__ __forceinline__ float ex2f(float x) { float y; asm("ex2.approx.f32 %0, %1;" : "=f"(y) : "f"(x)); return y; }
__device__ __forceinline__ float rcpf(float x) { float y; asm("rcp.approx.f32 %0, %1;" : "=f"(y) : "f"(x)); return y; }

// ---------------- std pass 1 (partials) + params (block 0, concurrent) -------
__global__ void __launch_bounds__(256)
k_std1(const float* __restrict__ y,
       const float* cmean, const float* cstd,
       const float* W_rom, const float* W_rlm, const float* W_rfm,
       const float* b0_yom, const float* W_b1_yom,
       const float* b0_ylm, const float* W_b2_ylm,
       const float* theltaC)
{
    __shared__ float ss[8], sq[8];
    const int tid = threadIdx.x;
    const int gi  = blockIdx.x * 256 + tid;

    // params are independent of the partial sums: block 0 / thread 255 does
    // them while everyone else reduces (no added critical path).
    if (blockIdx.x == 0 && tid == 255) {
        float eo  = expf(W_rom[0]);
        float el  = expf(W_rlm[0]);
        float den = eo + el + expf(W_rfm[0]);
        float a1  = W_b1_yom[0] / cstd[0];
        float a2  = W_b2_ylm[0] / SL_C;
        g_P0 = make_float4(expf(theltaC[0]),                    // thr
                           eo / den,                            // oo1
                           el / den,                            // ol1
                           -a1 * L2E);                          // a1n
        g_P1 = make_float4(-(b0_yom[0] - cmean[0] * a1) * L2E,  // k01n
                           -a2 * L2E,                           // a2n
                           -(b0_ylm[0] - ML_C * a2) * L2E,      // k02n
                           0.0f);
    }

    float a = 0.0f, b = 0.0f;
    if (gi < STD_N4) {
        // y + SPIN_LEN is 16B-aligned (100 floats = 400 bytes)
        float4 v = reinterpret_cast<const float4*>(y + SPIN_LEN)[gi];
        a = ((v.x + v.y) + (v.z + v.w));
        b = fmaf(v.x, v.x, fmaf(v.y, v.y, fmaf(v.z, v.z, v.w * v.w)));
    }
    #pragma unroll
    for (int o = 16; o > 0; o >>= 1) {
        a += __shfl_down_sync(0xffffffffu, a, o);
        b += __shfl_down_sync(0xffffffffu, b, o);
    }
    if ((tid & 31) == 0) { ss[tid >> 5] = a; sq[tid >> 5] = b; }
    __syncthreads();
    if (tid == 0) {
        float sa = 0.0f, sb = 0.0f;
        #pragma unroll
        for (int w = 0; w < 8; ++w) { sa += ss[w]; sb += sq[w]; }
        g_ps[blockIdx.x] = sa;
        g_pq[blockIdx.x] = sb;
    }
}

// ---------------- main chunked-warmup scan ----------------
// 512 blocks x 128 threads. Block shares one 536-step window (WARM prefix
// shared across all 128 chains). Thread t: 24 discarded + 4 emitted steps.
// Params arrive precomputed (2 broadcast float4 loads); the 196 std partials
// are block-reduced here (2 LDG/thread, fixed order -> identical everywhere).
__global__ void __launch_bounds__(TB)
k_scan(const float* __restrict__ x, float* __restrict__ out, int B)
{
    __shared__ float4 sw[SWIN4];
    __shared__ float  ob[10 * SOUT];
    __shared__ float  rs[8];         // 4 warp partial (sa,sb) pairs
    __shared__ float  sstd;

    const int tid    = threadIdx.x;
    const int base   = blockIdx.x * OUTB;   // first emitted global step
    const int wstart = base - WARM;         // window start (may be < 0)

    // ---- issue all global loads up front (latencies overlap) ----
    float2 xv[5];
    #pragma unroll
    for (int m = 0; m < 5; ++m) {
        int g = tid + TB * m;
        int i = wstart + g;
        xv[m] = make_float2(0.0f, 0.0f);
        if (g < NWB && i >= 0)
            xv[m] = reinterpret_cast<const float2*>(x)[i];
    }
    float pa = 0.0f, pb = 0.0f;
    if (tid < SB)      { pa += g_ps[tid];      pb += g_pq[tid]; }
    if (tid + TB < SB) { pa += g_ps[tid + TB]; pb += g_pq[tid + TB]; }
    const float4 P0 = g_P0, P1 = g_P1;       // broadcast loads (L2-hot)
    const float thr = P0.x, oo1 = P0.y, ol1 = P0.z, a1n = P0.w;
    const float k01n = P1.x, a2n = P1.y, k02n = P1.z;

    // ---- stage window + precompute ol(u2) ----
    // Zero-fill for steps < 0 keeps c == 0 exactly (m=min(0,thr)=0, olcc=0).
    #pragma unroll
    for (int m = 0; m < 5; ++m) {
        int g = tid + TB * m;
        if (g < NWB) {
            float ol = ol1 * rcpf(1.0f + ex2f(fmaf(xv[m].y, a2n, k02n)));
            if (wstart + g < 0) ol = 0.0f;
            sw[SK4(g)] = make_float4(xv[m].x, xv[m].y, ol, 0.0f);
        }
    }

    // ---- std final reduce (block-wide, fixed order -> deterministic) ----
    #pragma unroll
    for (int o = 16; o > 0; o >>= 1) {
        pa += __shfl_down_sync(0xffffffffu, pa, o);
        pb += __shfl_down_sync(0xffffffffu, pb, o);
    }
    if ((tid & 31) == 0) { rs[(tid >> 5) * 2] = pa; rs[(tid >> 5) * 2 + 1] = pb; }
    __syncthreads();                          // also covers window staging
    if (tid == 0) {
        float sa = (rs[0] + rs[2]) + (rs[4] + rs[6]);
        float sb = (rs[1] + rs[3]) + (rs[5] + rs[7]);
        const float n = (float)STD_N;
        float mean = sa / n;
        sstd = sqrtf((sb - sa * mean) / (n - 1.0f));
    }
    __syncthreads();
    const float stdv = sstd;

    const int g0 = tid * CHT;          // chain window start (multiple of 4)
    float c = 0.0f;

    // ---- warmup: divide-free, affine smem addressing ----
    // 4-aligned 4-step ranges never cross an 8-boundary -> (g)>>3 constant
    // per range -> base pointer + immediate offsets.
    // step: m = min(u1, thr-c); olcc = min(ol*c, u2); c' = fma(-oo1*c, s, (c-olcc)+m)
    #pragma unroll
    for (int k0 = 0; k0 < WARM; k0 += 4) {
        const float4* p = &sw[SK4(g0 + k0)];
        #pragma unroll
        for (int k = 0; k < 4; ++k) {
            float4 v = p[k];
            float s    = rcpf(1.0f + ex2f(fmaf(c, a1n, k01n)));
            float t    = oo1 * c;
            float olcc = fminf(v.z * c, v.y);
            float m    = fminf(v.x, thr - c);
            c = fmaf(-t, s, (c - olcc) + m);
        }
    }

    // ---- output phase: 4 steps into smem transpose buffer ----
    const int sb0 = CHT * tid + (tid >> 3);   // SKO(4*tid), k-invariant base
    {
        const float4* p = &sw[SK4(g0 + WARM)];
        #pragma unroll
        for (int k = 0; k < CHT; ++k) {
            float4 v = p[k];
            float* q = &ob[sb0 + k];

            float s    = rcpf(1.0f + ex2f(fmaf(c, a1n, k01n)));
            float oo   = oo1 * s;
            float ooc  = oo * c;
            float olc  = (c > 0.0f) ? fminf(v.z, v.y * rcpf(c)) : v.z;
            float olcc = olc * c;
            float px   = fmaxf(v.x + c - thr, 0.0f);
            float ib   = (v.x > 0.0f) ? px * rcpf(v.x) : 0.0f;
            float f    = (1.0f - oo) - olc;

            q[0 * SOUT] = ooc + px;   // h_n
            q[1 * SOUT] = c;          // c_n (pre-update)
            q[2 * SOUT] = v.z * c;    // l_n
            q[3 * SOUT] = olcc;       // lc_n
            q[4 * SOUT] = px;         // bp_n
            q[5 * SOUT] = ib;         // g_ib
            q[6 * SOUT] = oo;         // g_oo
            q[7 * SOUT] = v.z;        // g_ol
            q[8 * SOUT] = olc;        // g_olc
            q[9 * SOUT] = f;          // g_f

            c = ((c - ooc) - olcc) + (v.x - px);
        }
    }
    __syncthreads();

    // ---- coalesced flush (also produces h_nout and obs_std streams) ----
    #pragma unroll
    for (int st = 0; st < 10; ++st) {
        #pragma unroll
        for (int m = 0; m < OUTB / TB; ++m) {
            int t = tid + TB * m;
            out[(size_t)st * B + base + t] = ob[st * SOUT + t + (t >> 5)];
        }
    }
    float2* o2 = reinterpret_cast<float2*>(out + 10 * (size_t)B);
    #pragma unroll
    for (int m = 0; m < OUTB / TB; ++m) {
        int t = tid + TB * m;
        o2[base + t] = make_float2(ob[t + (t >> 5)], stdv);   // h_nout = [h, std]
        out[12 * (size_t)B + base + t] = stdv;                // obs_std
    }
}

// ---------------- launch ----------------
extern "C" void kernel_launch(void* const* d_in, const int* in_sizes, int n_in,
                              void* d_out, int out_size)
{
    const float* x = (const float*)d_in[0];
    const float* y = (const float*)d_in[1];
    float* out = (float*)d_out;
    const int B = in_sizes[0] / 2;   // 262144

    k_std1<<<SB, 256>>>(y,
                        (const float*)d_in[2], (const float*)d_in[3],
                        (const float*)d_in[4], (const float*)d_in[5],
                        (const float*)d_in[6], (const float*)d_in[7],
                        (const float*)d_in[8], (const float*)d_in[9],
                        (const float*)d_in[10], (const float*)d_in[11]);

    const int blocks = B / OUTB;     // 512 blocks x 128 threads
    k_scan<<<blocks, TB>>>(x, out, B);
}

// round 14
// speedup vs baseline: 1.2206x; 1.0050x over previous
#include <cuda_runtime.h>
#include <math.h>

// ---------------- constants (from reference) ----------------
#define SPIN_LEN   100
#define TRAIN_LEN  200000
#define ML_C       2.9086f
#define SL_C       1.898f
#define L2E        1.4426950408889634f

#define CHT     2                    // output steps per thread
#define TB      128                  // threads per scan block (4 warps)
#define WARM    16                   // discarded convergence steps
#define OUTB    (TB * CHT)           // 256 output steps per block
#define NWB     (WARM + OUTB)        // 272-step shared input window per block
#define SK4(g)  ((g) + ((g) >> 3))   // float4 skew: conflict-free at stride 2
#define SWIN4   (SK4(NWB - 1) + 1)   // 305
#define SKO(t)  ((t) + ((t) >> 5))   // float skew for output transpose buffer
#define SOUT    (SKO(OUTB - 1) + 1)  // 263

#define STD_N   (TRAIN_LEN - SPIN_LEN)   // 199900 floats = 49975 float4 exactly
#define STD_N4  (STD_N / 4)              // 49975
#define SB      196                      // 196*256 = 50176 threads >= 49975

// ---------------- device scratch ----------------
__device__ float g_ps[SB];
__device__ float g_pq[SB];

__device__ __forceinline__ float ex2f(float x) { float y; asm("ex2.approx.f32 %0, %1;" : "=f"(y) : "f"(x)); return y; }
__device__ __forceinline__ float rcpf(float x) { float y; asm("rcp.approx.f32 %0, %1;" : "=f"(y) : "f"(x)); return y; }

// ---------------- std pass 1: single-wave float4 partial sums (no tail) -----
__global__ void __launch_bounds__(256)
k_std1(const float* __restrict__ y)
{
    __shared__ float ss[8], sq[8];
    const int tid = threadIdx.x;
    const int gi  = blockIdx.x * 256 + tid;

    float a = 0.0f, b = 0.0f;
    if (gi < STD_N4) {
        // y + SPIN_LEN is 16B-aligned (100 floats = 400 bytes)
        float4 v = reinterpret_cast<const float4*>(y + SPIN_LEN)[gi];
        a = ((v.x + v.y) + (v.z + v.w));
        b = fmaf(v.x, v.x, fmaf(v.y, v.y, fmaf(v.z, v.z, v.w * v.w)));
    }
    #pragma unroll
    for (int o = 16; o > 0; o >>= 1) {
        a += __shfl_down_sync(0xffffffffu, a, o);
        b += __shfl_down_sync(0xffffffffu, b, o);
    }
    if ((tid & 31) == 0) { ss[tid >> 5] = a; sq[tid >> 5] = b; }
    __syncthreads();
    if (tid == 0) {
        float sa = 0.0f, sb = 0.0f;
        #pragma unroll
        for (int w = 0; w < 8; ++w) { sa += ss[w]; sb += sq[w]; }
        g_ps[blockIdx.x] = sa;
        g_pq[blockIdx.x] = sb;
    }
}

// ---------------- main chunked-warmup scan ----------------
// 1024 blocks x 128 threads (4096 warps, ~7/SMSP). Block shares one 272-step
// window; thread t: 16 discarded + 2 emitted steps. Warp 0 derives the scalar
// params into smem (overlapping everyone's x LDGs); the 196 std partials are
// block-reduced (fixed order -> deterministic, identical across blocks).
__global__ void __launch_bounds__(TB)
k_scan(const float* __restrict__ x, float* __restrict__ out, int B,
       const float* cmean, const float* cstd,
       const float* W_rom, const float* W_rlm, const float* W_rfm,
       const float* b0_yom, const float* W_b1_yom,
       const float* b0_ylm, const float* W_b2_ylm,
       const float* theltaC)
{
    __shared__ float4 sw[SWIN4];
    __shared__ float  ob[10 * SOUT];
    __shared__ float  rs[8];         // 4 warp (sa,sb) partials
    __shared__ float  sp[8];         // thr, oo1, ol1, a1n, k01n, a2n, k02n
    __shared__ float  sstd;

    const int tid    = threadIdx.x;
    const int base   = blockIdx.x * OUTB;   // first emitted global step
    const int wstart = base - WARM;         // window start (may be < 0)

    // ---- issue all global loads up front (latencies overlap) ----
    float2 xv[3];
    #pragma unroll
    for (int m = 0; m < 3; ++m) {
        int g = tid + TB * m;
        int i = wstart + g;
        xv[m] = make_float2(0.0f, 0.0f);
        if (g < NWB && i >= 0)
            xv[m] = reinterpret_cast<const float2*>(x)[i];
    }
    float pa = 0.0f, pb = 0.0f;
    if (tid < SB)      { pa += g_ps[tid];      pb += g_pq[tid]; }
    if (tid + TB < SB) { pa += g_ps[tid + TB]; pb += g_pq[tid + TB]; }

    // ---- warp 0: derive scalar params (uniform loads, redundant per lane) ----
    if (tid < 32) {
        float eo  = expf(W_rom[0]);
        float el  = expf(W_rlm[0]);
        float den = eo + el + expf(W_rfm[0]);
        float a1  = W_b1_yom[0] / cstd[0];
        float a2  = W_b2_ylm[0] / SL_C;
        if (tid == 0) {
            sp[0] = expf(theltaC[0]);                    // thr
            sp[1] = eo / den;                            // oo1
            sp[2] = el / den;                            // ol1
            sp[3] = -a1 * L2E;                           // a1n
            sp[4] = -(b0_yom[0] - cmean[0] * a1) * L2E;  // k01n
            sp[5] = -a2 * L2E;                           // a2n
            sp[6] = -(b0_ylm[0] - ML_C * a2) * L2E;      // k02n
        }
    }

    // ---- std partial reduce (warp level) ----
    #pragma unroll
    for (int o = 16; o > 0; o >>= 1) {
        pa += __shfl_down_sync(0xffffffffu, pa, o);
        pb += __shfl_down_sync(0xffffffffu, pb, o);
    }
    if ((tid & 31) == 0) { rs[(tid >> 5) * 2] = pa; rs[(tid >> 5) * 2 + 1] = pb; }
    __syncthreads();                           // sp + rs visible

    const float thr = sp[0], oo1 = sp[1], ol1 = sp[2], a1n = sp[3];
    const float k01n = sp[4], a2n = sp[5], k02n = sp[6];

    // ---- stage window + precompute ol(u2) ----
    // Zero-fill for steps < 0 keeps c == 0 exactly (m=min(0,thr)=0, olcc=0).
    #pragma unroll
    for (int m = 0; m < 3; ++m) {
        int g = tid + TB * m;
        if (g < NWB) {
            float ol = ol1 * rcpf(1.0f + ex2f(fmaf(xv[m].y, a2n, k02n)));
            if (wstart + g < 0) ol = 0.0f;
            sw[SK4(g)] = make_float4(xv[m].x, xv[m].y, ol, 0.0f);
        }
    }
    if (tid == 0) {
        float sa = (rs[0] + rs[2]) + (rs[4] + rs[6]);
        float sb = (rs[1] + rs[3]) + (rs[5] + rs[7]);
        const float n = (float)STD_N;
        float mean = sa / n;
        sstd = sqrtf((sb - sa * mean) / (n - 1.0f));
    }
    __syncthreads();                           // sw + sstd visible
    const float stdv = sstd;

    const int g0 = tid * CHT;          // chain window start
    float c = 0.0f;

    // ---- warmup: divide-free ----
    // step: m = min(u1, thr-c); olcc = min(ol*c, u2); c' = fma(-oo1*c, s, (c-olcc)+m)
    #pragma unroll
    for (int k = 0; k < WARM; ++k) {
        float4 v = sw[SK4(g0 + k)];
        float s    = rcpf(1.0f + ex2f(fmaf(c, a1n, k01n)));
        float t    = oo1 * c;
        float olcc = fminf(v.z * c, v.y);
        float m    = fminf(v.x, thr - c);
        c = fmaf(-t, s, (c - olcc) + m);
    }

    // ---- output phase: 2 steps into smem transpose buffer ----
    const int sb0 = CHT * tid + (tid >> 4);   // SKO(2*tid), k-invariant base
    #pragma unroll
    for (int k = 0; k < CHT; ++k) {
        float4 v = sw[SK4(g0 + WARM + k)];
        float* q = &ob[sb0 + k];

        float s    = rcpf(1.0f + ex2f(fmaf(c, a1n, k01n)));
        float oo   = oo1 * s;
        float ooc  = oo * c;
        float olc  = (c > 0.0f) ? fminf(v.z, v.y * rcpf(c)) : v.z;
        float olcc = olc * c;
        float px   = fmaxf(v.x + c - thr, 0.0f);
        float ib   = (v.x > 0.0f) ? px * rcpf(v.x) : 0.0f;
        float f    = (1.0f - oo) - olc;

        q[0 * SOUT] = ooc + px;   // h_n
        q[1 * SOUT] = c;          // c_n (pre-update)
        q[2 * SOUT] = v.z * c;    // l_n
        q[3 * SOUT] = olcc;       // lc_n
        q[4 * SOUT] = px;         // bp_n
        q[5 * SOUT] = ib;         // g_ib
        q[6 * SOUT] = oo;         // g_oo
        q[7 * SOUT] = v.z;        // g_ol
        q[8 * SOUT] = olc;        // g_olc
        q[9 * SOUT] = f;          // g_f

        c = ((c - ooc) - olcc) + (v.x - px);
    }
    __syncthreads();

    // ---- coalesced flush (also produces h_nout and obs_std streams) ----
    #pragma unroll
    for (int st = 0; st < 10; ++st) {
        #pragma unroll
        for (int m = 0; m < OUTB / TB; ++m) {
            int t = tid + TB * m;
            out[(size_t)st * B + base + t] = ob[st * SOUT + t + (t >> 5)];
        }
    }
    float2* o2 = reinterpret_cast<float2*>(out + 10 * (size_t)B);
    #pragma unroll
    for (int m = 0; m < OUTB / TB; ++m) {
        int t = tid + TB * m;
        o2[base + t] = make_float2(ob[t + (t >> 5)], stdv);   // h_nout = [h, std]
        out[12 * (size_t)B + base + t] = stdv;                // obs_std
    }
}

// ---------------- launch ----------------
extern "C" void kernel_launch(void* const* d_in, const int* in_sizes, int n_in,
                              void* d_out, int out_size)
{
    const float* x = (const float*)d_in[0];
    const float* y = (const float*)d_in[1];
    float* out = (float*)d_out;
    const int B = in_sizes[0] / 2;   // 262144

    k_std1<<<SB, 256>>>(y);

    const int blocks = B / OUTB;     // 1024 blocks x 128 threads
    k_scan<<<blocks, TB>>>(x, out, B,
                           (const float*)d_in[2], (const float*)d_in[3],
                           (const float*)d_in[4], (const float*)d_in[5],
                           (const float*)d_in[6], (const float*)d_in[7],
                           (const float*)d_in[8], (const float*)d_in[9],
                           (const float*)d_in[10], (const float*)d_in[11]);
}

// round 15
// speedup vs baseline: 1.2617x; 1.0337x over previous
#include <cuda_runtime.h>
#include <math.h>

// ---------------- constants (from reference) ----------------
#define SPIN_LEN   100
#define TRAIN_LEN  200000
#define ML_C       2.9086f
#define SL_C       1.898f
#define L2E        1.4426950408889634f

#define CHT     4                    // output steps per thread (contiguous in gmem!)
#define TB      128                  // threads per scan block (4 warps)
#define WARM    24                   // discarded convergence steps
#define OUTB    (TB * CHT)           // 512 output steps per block
#define NWB     (WARM + OUTB)        // 536-step shared input window per block
#define SK4(g)  ((g) + ((g) >> 3))   // float4 skew: conflict-free at stride 4
#define SWIN4   (SK4(NWB - 1) + 1)   // 602

#define STD_N   (TRAIN_LEN - SPIN_LEN)   // 199900 floats = 49975 float4 exactly
#define STD_N4  (STD_N / 4)              // 49975
#define SB      196                      // 196*256 = 50176 threads >= 49975

// ---------------- device scratch ----------------
__device__ float g_ps[SB];
__device__ float g_pq[SB];

__device__ __forceinline__ float ex2f(float x) { float y; asm("ex2.approx.f32 %0, %1;" : "=f"(y) : "f"(x)); return y; }
__device__ __forceinline__ float rcpf(float x) { float y; asm("rcp.approx.f32 %0, %1;" : "=f"(y) : "f"(x)); return y; }

// ---------------- std pass 1: single-wave float4 partial sums (no tail) -----
__global__ void __launch_bounds__(256)
k_std1(const float* __restrict__ y)
{
    __shared__ float ss[8], sq[8];
    const int tid = threadIdx.x;
    const int gi  = blockIdx.x * 256 + tid;

    float a = 0.0f, b = 0.0f;
    if (gi < STD_N4) {
        // y + SPIN_LEN is 16B-aligned (100 floats = 400 bytes)
        float4 v = reinterpret_cast<const float4*>(y + SPIN_LEN)[gi];
        a = ((v.x + v.y) + (v.z + v.w));
        b = fmaf(v.x, v.x, fmaf(v.y, v.y, fmaf(v.z, v.z, v.w * v.w)));
    }
    #pragma unroll
    for (int o = 16; o > 0; o >>= 1) {
        a += __shfl_down_sync(0xffffffffu, a, o);
        b += __shfl_down_sync(0xffffffffu, b, o);
    }
    if ((tid & 31) == 0) { ss[tid >> 5] = a; sq[tid >> 5] = b; }
    __syncthreads();
    if (tid == 0) {
        float sa = 0.0f, sb = 0.0f;
        #pragma unroll
        for (int w = 0; w < 8; ++w) { sa += ss[w]; sb += sq[w]; }
        g_ps[blockIdx.x] = sa;
        g_pq[blockIdx.x] = sb;
    }
}

// ---------------- main chunked-warmup scan ----------------
// 512 blocks x 128 threads. Block shares one 536-step input window; thread t
// runs 24 discarded + 4 emitted steps, and since its 4 emitted steps are
// out[st*B + base + 4t .. 4t+3] (contiguous!), results accumulate in registers
// and flush as coalesced STG.128 — no output smem transpose at all.
__global__ void __launch_bounds__(TB)
k_scan(const float* __restrict__ x, float* __restrict__ out, int B,
       const float* cmean, const float* cstd,
       const float* W_rom, const float* W_rlm, const float* W_rfm,
       const float* b0_yom, const float* W_b1_yom,
       const float* b0_ylm, const float* W_b2_ylm,
       const float* theltaC)
{
    __shared__ float4 sw[SWIN4];
    __shared__ float  rs[8];         // 4 warp (sa,sb) partials
    __shared__ float  sp[8];         // thr, oo1, ol1, a1n, k01n, a2n, k02n
    __shared__ float  sstd;

    const int tid    = threadIdx.x;
    const int base   = blockIdx.x * OUTB;   // first emitted global step
    const int wstart = base - WARM;         // window start (may be < 0)

    // ---- issue all global loads up front (latencies overlap) ----
    float2 xv[5];
    #pragma unroll
    for (int m = 0; m < 5; ++m) {
        int g = tid + TB * m;
        int i = wstart + g;
        xv[m] = make_float2(0.0f, 0.0f);
        if (g < NWB && i >= 0)
            xv[m] = reinterpret_cast<const float2*>(x)[i];
    }
    float pa = 0.0f, pb = 0.0f;
    if (tid < SB)      { pa += g_ps[tid];      pb += g_pq[tid]; }
    if (tid + TB < SB) { pa += g_ps[tid + TB]; pb += g_pq[tid + TB]; }

    // ---- warp 0: derive scalar params (overlaps other warps' work) ----
    if (tid == 0) {
        float eo  = expf(W_rom[0]);
        float el  = expf(W_rlm[0]);
        float den = eo + el + expf(W_rfm[0]);
        float a1  = W_b1_yom[0] / cstd[0];
        float a2  = W_b2_ylm[0] / SL_C;
        sp[0] = expf(theltaC[0]);                    // thr
        sp[1] = eo / den;                            // oo1
        sp[2] = el / den;                            // ol1
        sp[3] = -a1 * L2E;                           // a1n
        sp[4] = -(b0_yom[0] - cmean[0] * a1) * L2E;  // k01n
        sp[5] = -a2 * L2E;                           // a2n
        sp[6] = -(b0_ylm[0] - ML_C * a2) * L2E;      // k02n
    }

    // ---- std partial reduce (warp level) ----
    #pragma unroll
    for (int o = 16; o > 0; o >>= 1) {
        pa += __shfl_down_sync(0xffffffffu, pa, o);
        pb += __shfl_down_sync(0xffffffffu, pb, o);
    }
    if ((tid & 31) == 0) { rs[(tid >> 5) * 2] = pa; rs[(tid >> 5) * 2 + 1] = pb; }
    __syncthreads();                           // sp + rs visible

    const float thr = sp[0], oo1 = sp[1], ol1 = sp[2], a1n = sp[3];
    const float k01n = sp[4], a2n = sp[5], k02n = sp[6];

    // ---- stage window + precompute ol(u2) ----
    // Zero-fill for steps < 0 keeps c == 0 exactly (m=min(0,thr)=0, olcc=0).
    #pragma unroll
    for (int m = 0; m < 5; ++m) {
        int g = tid + TB * m;
        if (g < NWB) {
            float ol = ol1 * rcpf(1.0f + ex2f(fmaf(xv[m].y, a2n, k02n)));
            if (wstart + g < 0) ol = 0.0f;
            sw[SK4(g)] = make_float4(xv[m].x, xv[m].y, ol, 0.0f);
        }
    }
    if (tid == 0) {
        float sa = (rs[0] + rs[2]) + (rs[4] + rs[6]);
        float sb = (rs[1] + rs[3]) + (rs[5] + rs[7]);
        const float n = (float)STD_N;
        float mean = sa / n;
        sstd = sqrtf((sb - sa * mean) / (n - 1.0f));
    }
    __syncthreads();                           // sw + sstd visible
    const float stdv = sstd;

    const int g0 = tid * CHT;          // chain window start (multiple of 4)
    float c = 0.0f;

    // ---- warmup: divide-free, affine smem addressing ----
    // 4-aligned 4-step ranges never cross an 8-boundary -> (g)>>3 constant
    // per range -> base pointer + immediate offsets.
    // step: m = min(u1, thr-c); olcc = min(ol*c, u2); c' = fma(-oo1*c, s, (c-olcc)+m)
    #pragma unroll
    for (int k0 = 0; k0 < WARM; k0 += 4) {
        const float4* p = &sw[SK4(g0 + k0)];
        #pragma unroll
        for (int k = 0; k < 4; ++k) {
            float4 v = p[k];
            float s    = rcpf(1.0f + ex2f(fmaf(c, a1n, k01n)));
            float t    = oo1 * c;
            float olcc = fminf(v.z * c, v.y);
            float m    = fminf(v.x, thr - c);
            c = fmaf(-t, s, (c - olcc) + m);
        }
    }

    // ---- output phase: 4 steps, results in registers (r[stream][k]) ----
    float r[10][CHT];
    {
        const float4* p = &sw[SK4(g0 + WARM)];
        #pragma unroll
        for (int k = 0; k < CHT; ++k) {
            float4 v = p[k];

            float s    = rcpf(1.0f + ex2f(fmaf(c, a1n, k01n)));
            float oo   = oo1 * s;
            float ooc  = oo * c;
            float olc  = (c > 0.0f) ? fminf(v.z, v.y * rcpf(c)) : v.z;
            float olcc = olc * c;
            float px   = fmaxf(v.x + c - thr, 0.0f);
            float ib   = (v.x > 0.0f) ? px * rcpf(v.x) : 0.0f;
            float f    = (1.0f - oo) - olc;

            r[0][k] = ooc + px;   // h_n
            r[1][k] = c;          // c_n (pre-update)
            r[2][k] = v.z * c;    // l_n
            r[3][k] = olcc;       // lc_n
            r[4][k] = px;         // bp_n
            r[5][k] = ib;         // g_ib
            r[6][k] = oo;         // g_oo
            r[7][k] = v.z;        // g_ol
            r[8][k] = olc;        // g_olc
            r[9][k] = f;          // g_f

            c = ((c - ooc) - olcc) + (v.x - px);
        }
    }

    // ---- direct coalesced flush: STG.128 per stream ----
    const int o0 = base + CHT * tid;   // 16B-aligned (multiple of 4 floats)
    #pragma unroll
    for (int st = 0; st < 10; ++st) {
        *reinterpret_cast<float4*>(out + (size_t)st * B + o0) =
            make_float4(r[st][0], r[st][1], r[st][2], r[st][3]);
    }
    // h_nout = interleaved [h, std] pairs; obs_std = splat
    float4* o2 = reinterpret_cast<float4*>(out + 10 * (size_t)B + 2 * (size_t)o0);
    o2[0] = make_float4(r[0][0], stdv, r[0][1], stdv);
    o2[1] = make_float4(r[0][2], stdv, r[0][3], stdv);
    *reinterpret_cast<float4*>(out + 12 * (size_t)B + o0) =
        make_float4(stdv, stdv, stdv, stdv);
}

// ---------------- launch ----------------
extern "C" void kernel_launch(void* const* d_in, const int* in_sizes, int n_in,
                              void* d_out, int out_size)
{
    const float* x = (const float*)d_in[0];
    const float* y = (const float*)d_in[1];
    float* out = (float*)d_out;
    const int B = in_sizes[0] / 2;   // 262144

    k_std1<<<SB, 256>>>(y);

    const int blocks = B / OUTB;     // 512 blocks x 128 threads
    k_scan<<<blocks, TB>>>(x, out, B,
                           (const float*)d_in[2], (const float*)d_in[3],
                           (const float*)d_in[4], (const float*)d_in[5],
                           (const float*)d_in[6], (const float*)d_in[7],
                           (const float*)d_in[8], (const float*)d_in[9],
                           (const float*)d_in[10], (const float*)d_in[11]);
}